// round 16
// baseline (speedup 1.0000x reference)
#include <cuda_runtime.h>
#include <cuda_fp16.h>
#include <cstdint>

// ---- lc_kernel smem layout (32-bit words) ----
#define WSM_OFF   24576         // after 3 u slots (3 * 8192 words)
#define WQS 552                 // w q-stride
#define WLS 34                  // w l-stride (32 o + 2 pad)
#define WBUFW 4416              // 8 * 552 (one w slot)
#define KOFF_OFF  37824         // after 3 w slots
#define SEP_BS 34
#define SEP_PS 2176             // 64 * 34
#define SMEM_BYTES (38400 * 4)

__device__ __align__(256) __half g_xh[64 * 34 * 34 * 64];  // [c][hp][wp][b] fp16

__device__ __forceinline__ uint32_t f16x2(float hi, float lo) {
    uint32_t d; asm("cvt.rn.f16x2.f32 %0,%1,%2;" : "=r"(d) : "f"(hi), "f"(lo)); return d;
}
__device__ __forceinline__ uint32_t s2u(const void* p) {
    uint32_t a;
    asm("{.reg .u64 t; cvta.to.shared.u64 t,%1; cvt.u32.u64 %0,t;}" : "=r"(a) : "l"(p));
    return a;
}
#define MMAF16(d, a, b) asm volatile( \
    "mma.sync.aligned.m16n8k16.row.col.f32.f16.f16.f32 " \
    "{%0,%1,%2,%3},{%4,%5,%6,%7},{%8,%9},{%0,%1,%2,%3};" \
    : "+f"((d)[0]), "+f"((d)[1]), "+f"((d)[2]), "+f"((d)[3]) \
    : "r"((a)[0]), "r"((a)[1]), "r"((a)[2]), "r"((a)[3]), "r"((b)[0]), "r"((b)[1]))
#define BAR_SYNC(id)   asm volatile("bar.sync %0, 640;"   :: "r"(id) : "memory")
#define BAR_ARRIVE(id) asm volatile("bar.arrive %0, 640;" :: "r"(id) : "memory")

// ---------------------------------------------------------------------------
__global__ void prep_kernel(const float* __restrict__ x) {
    int tid = threadIdx.x;
    if (blockIdx.x >= 2048) {
        int idx = (blockIdx.x - 2048) * 256 + tid;     // 64c * 132 cells * 8
        if (idx >= 64 * 132 * 8) return;
        int g8 = idx & 7, r = idx >> 3;
        int c = r / 132, cell = r % 132;
        int hp, wp;
        if (cell < 34)       { hp = 0;  wp = cell; }
        else if (cell < 68)  { hp = 33; wp = cell - 34; }
        else if (cell < 100) { hp = cell - 68 + 1;  wp = 0; }
        else                 { hp = cell - 100 + 1; wp = 33; }
        *(uint4*)&g_xh[((c * 34 + hp) * 34 + wp) * 64 + g8 * 8] = make_uint4(0, 0, 0, 0);
        return;
    }
    __shared__ float t[32][65];
    int c = blockIdx.x & 63, h = blockIdx.x >> 6;
    int w = tid & 31, b0 = tid >> 5;
#pragma unroll
    for (int p = 0; p < 8; p++)
        t[w][b0 * 8 + p] = x[(((b0 * 8 + p) * 64 + c) * 32 + h) * 32 + w];
    __syncthreads();
    int b = tid & 63, wq = tid >> 6;
#pragma unroll
    for (int p = 0; p < 8; p++) {
        int ww = wq * 8 + p;
        g_xh[((c * 34 + h + 1) * 34 + ww + 1) * 64 + b] = __float2half_rn(t[ww][b]);
    }
}

// ---------------------------------------------------------------------------
// lc_kernel: 128 CTAs = 64 l-tiles x 2 o-halves. CTA = 16 l x 32 o x 64 b.
// 640 threads: warps 0-15 consumers (warp=pixel, M64xN32), warps 16-19 producers.
// Producers: u via cp.async (3 slots, swizzled), w via l-contig LDG.32 ->
// f16x2 -> conflict-free STS (3 slots). Named barriers full/free per slot.
// ---------------------------------------------------------------------------
__global__ __launch_bounds__(640, 1)
void lc_kernel(const float* __restrict__ weight, const float* __restrict__ bias,
               float* __restrict__ out) {
    extern __shared__ uint32_t sm[];
    uint32_t* wsm = sm + WSM_OFF;
    int* koff = (int*)(sm + KOFF_OFF);
    const uint32_t sbase = s2u(sm);

    const int tid = threadIdx.x, lane = tid & 31, wrp = tid >> 5;
    const int l_tile = blockIdx.x >> 1, o0 = (blockIdx.x & 1) << 5;
    const int l0 = l_tile << 4;
    const int h = l0 >> 5, w0 = l0 & 31;            // 16-aligned tile: single h

    for (int k = tid; k < 576; k += 640) {
        int c = k / 9, r = k - 9 * c, i = r / 3, j = r - 3 * i;
        koff[k] = (c * 1156 + i * 34 + j) * 64;     // half-element units
    }
    __syncthreads();

    if (wrp < 16) {
        // ================= CONSUMERS =================
        const int pix = wrp;
        const int cq = lane & 3, rr = lane >> 2;
        const int kr = (lane & 7) | ((lane & 16) >> 1);
        const int bh = (lane >> 3) & 1;
        const int k7 = kr & 7;
        const uint32_t lm_row = sbase + (uint32_t)(pix * 2048 + kr * 128);

        float acc[16][4];
#pragma unroll
        for (int i = 0; i < 16; i++)
#pragma unroll
            for (int j = 0; j < 4; j++) acc[i][j] = 0.f;

        int s = 0;
        for (int ch = 0; ch < 36; ch++) {
            BAR_SYNC(1 + s);
            const uint32_t* B = wsm + s * WBUFW + cq * WQS + pix * WLS + rr;
            uint32_t bfr[4][2];
#pragma unroll
            for (int nt = 0; nt < 4; nt++) {
                bfr[nt][0] = B[nt * 8];
                bfr[nt][1] = B[4 * WQS + nt * 8];
            }
            const uint32_t abase = lm_row + (uint32_t)s * 32768u;
#pragma unroll
            for (int mt = 0; mt < 4; mt++) {
                uint32_t a[4];
                uint32_t ad = abase + (uint32_t)((((2 * mt + bh) ^ k7) << 4));
                asm volatile("ldmatrix.sync.aligned.m8n8.x4.trans.shared.b16 "
                             "{%0,%1,%2,%3},[%4];"
                             : "=r"(a[0]), "=r"(a[1]), "=r"(a[2]), "=r"(a[3]) : "r"(ad));
#pragma unroll
                for (int nt = 0; nt < 4; nt++)
                    MMAF16(acc[mt * 4 + nt], a, bfr[nt]);
            }
            BAR_ARRIVE(4 + s);
            s = (s == 2) ? 0 : s + 1;
        }
        __syncthreads();

        // ---- epilogue: sep[pix][b][o] staging, then 64B coalesced rows ----
        float* sep = (float*)sm;
#pragma unroll
        for (int mt = 0; mt < 4; mt++)
#pragma unroll
            for (int nt = 0; nt < 4; nt++) {
                const float* d = acc[mt * 4 + nt];
                int b = mt * 16 + rr, o = nt * 8 + 2 * cq;
                float* pp = sep + pix * SEP_PS + b * SEP_BS + o;
                *(float2*)pp                = make_float2(d[0], d[1]);
                *(float2*)(pp + 8 * SEP_BS) = make_float2(d[2], d[3]);
            }
        __syncthreads();
#pragma unroll
        for (int it = 0; it < 4; it++) {
            int unit = tid + (it << 9);
            int o = unit & 31, b = unit >> 5;
            float v[16];
#pragma unroll
            for (int l = 0; l < 16; l++) v[l] = ((float*)sm)[l * SEP_PS + b * SEP_BS + o];
            const float* bp = bias + (size_t)(o0 + o) * 1024 + l0;
            float* dp = out + ((size_t)(b * 64 + o0 + o)) * 1024 + l0;
#pragma unroll
            for (int g = 0; g < 4; g++) {
                float4 bv = *(const float4*)(bp + 4 * g);
                *(float4*)(dp + 4 * g) = make_float4(v[4 * g] + bv.x, v[4 * g + 1] + bv.y,
                                                     v[4 * g + 2] + bv.z, v[4 * g + 3] + bv.w);
            }
        }
    } else {
        // ================= PRODUCERS (warps 16-19, 128 threads) =================
        const int p = tid - 512;
        const int wpl = p >> 5;                 // producer warp 0..3
        const int l_ln = lane & 15;             // l owned by this lane
        const int oh = lane >> 4;               // o parity
        // u mapping: 8 b-segs x 16 k, 16 l's each
        const int us8 = p & 7, uk = p >> 3;     // uk 0..15
        const __half* ubase = g_xh + (h * 34 + w0) * 64 + us8 * 8;
        const uint32_t udst0 = sbase + (uint32_t)(uk * 128 + ((us8 ^ (uk & 7)) << 4));
        // w mapping: o = o0 + 8*wpl + 2*j + oh, k 0..15, l = l_ln
        const float* wbase = weight + (size_t)(o0 + 8 * wpl + oh) * 589824 + l0 + l_ln;

        float rA[32], rB[32];
        auto ldgA = [&](int ch) {               // j = 0,1
#pragma unroll
            for (int j = 0; j < 2; j++)
#pragma unroll
                for (int k = 0; k < 16; k++)
                    rA[j * 16 + k] = __ldg(wbase + (size_t)(2 * j) * 589824
                                                 + (size_t)(ch * 16 + k) * 1024);
        };
        auto ldgB = [&](int ch) {               // j = 2,3
#pragma unroll
            for (int j = 0; j < 2; j++)
#pragma unroll
                for (int k = 0; k < 16; k++)
                    rB[j * 16 + k] = __ldg(wbase + (size_t)(2 * j + 4) * 589824
                                                 + (size_t)(ch * 16 + k) * 1024);
        };
        auto stsA = [&](int s) {
            uint32_t* d0 = wsm + s * WBUFW + l_ln * WLS + 8 * wpl + oh;
#pragma unroll
            for (int j = 0; j < 2; j++)
#pragma unroll
                for (int q = 0; q < 8; q++)
                    d0[q * WQS + 2 * j] = f16x2(rA[j * 16 + 2 * q + 1], rA[j * 16 + 2 * q]);
        };
        auto stsB = [&](int s) {
            uint32_t* d0 = wsm + s * WBUFW + l_ln * WLS + 8 * wpl + oh + 4;
#pragma unroll
            for (int j = 0; j < 2; j++)
#pragma unroll
                for (int q = 0; q < 8; q++)
                    d0[q * WQS + 2 * j] = f16x2(rB[j * 16 + 2 * q + 1], rB[j * 16 + 2 * q]);
        };

        ldgA(0); ldgB(0);
        int s = 0;
        for (int ch = 0; ch < 36; ch++) {
            if (ch >= 3) BAR_SYNC(4 + s);
            // u cp.async for this chunk
            {
                int ko = koff[ch * 16 + uk];
                uint32_t d = udst0 + (uint32_t)s * 32768u;
#pragma unroll
                for (int l = 0; l < 16; l++)
                    asm volatile("cp.async.cg.shared.global [%0],[%1],16;"
                                 :: "r"(d + (uint32_t)l * 2048u),
                                    "l"(ubase + l * 64 + ko));
                asm volatile("cp.async.commit_group;" ::: "memory");
            }
            stsA(s);
            if (ch < 35) ldgA(ch + 1);
            stsB(s);
            if (ch < 35) ldgB(ch + 1);
            asm volatile("cp.async.wait_group 0;" ::: "memory");
            BAR_ARRIVE(1 + s);
            s = (s == 2) ? 0 : s + 1;
        }
        __syncthreads();   // epilogue staging barrier (consumers write sep)
        __syncthreads();   // epilogue output barrier
    }
}

// ---------------------------------------------------------------------------
extern "C" void kernel_launch(void* const* d_in, const int* in_sizes, int n_in,
                              void* d_out, int out_size) {
    const float* x      = (const float*)d_in[0];
    const float* weight = (const float*)d_in[1];
    const float* bias   = (const float*)d_in[2];
    float* out = (float*)d_out;

    cudaFuncSetAttribute(lc_kernel, cudaFuncAttributeMaxDynamicSharedMemorySize, SMEM_BYTES);

    prep_kernel<<<2048 + 264, 256>>>(x);
    lc_kernel<<<128, 640, SMEM_BYTES>>>(weight, bias, out);
}